// round 1
// baseline (speedup 1.0000x reference)
#include <cuda_runtime.h>
#include <cuda_bf16.h>

// Problem constants
#define BATCH    16
#define N_COARSE 1024
#define N_FINE   4096
#define C_IN     256
#define C_SKIP   128
#define C_HID    256
#define NC_TOT   (BATCH * N_COARSE)   // 16384
#define NF_TOT   (BATCH * N_FINE)     // 65536

// Scratch (device globals; no runtime allocation allowed)
__device__ float g_y[NC_TOT * C_HID];     // y = x @ W1a          (16 MB)
__device__ float g_h1[NF_TOT * C_HID];    // hidden activations   (64 MB)
__device__ int   g_idx[NF_TOT * 3];       // knn indices (global coarse rows)
__device__ float g_w[NF_TOT * 3];         // normalized inverse-d2 weights

// ---------------------------------------------------------------------------
// Kernel 1: brute-force kNN (k=3) per cloud + normalized weights
// grid = BATCH * (N_FINE/128), block = 128
// ---------------------------------------------------------------------------
__global__ __launch_bounds__(128) void knn_kernel(
    const float* __restrict__ pos,        // [NC_TOT, 3]
    const float* __restrict__ pos_skip,   // [NF_TOT, 3]
    int* __restrict__ gidx, float* __restrict__ gw)
{
    __shared__ float sx[N_COARSE], sy[N_COARSE], sz[N_COARSE];
    const int chunks = N_FINE / 128;              // 32
    const int b = blockIdx.x / chunks;
    const int chunk = blockIdx.x % chunks;
    const int tid = threadIdx.x;

    const float* pc = pos + (size_t)b * N_COARSE * 3;
    for (int i = tid; i < N_COARSE; i += 128) {
        sx[i] = pc[i * 3 + 0];
        sy[i] = pc[i * 3 + 1];
        sz[i] = pc[i * 3 + 2];
    }
    __syncthreads();

    const int f = b * N_FINE + chunk * 128 + tid;
    const float px = pos_skip[f * 3 + 0];
    const float py = pos_skip[f * 3 + 1];
    const float pz = pos_skip[f * 3 + 2];

    float d0 = 3.4e38f, d1 = 3.4e38f, d2 = 3.4e38f;
    int   i0 = 0, i1 = 0, i2 = 0;

    #pragma unroll 4
    for (int j = 0; j < N_COARSE; j++) {
        float dx = px - sx[j], dy = py - sy[j], dz = pz - sz[j];
        float d = dx * dx + dy * dy + dz * dz;
        if (d < d2) {
            if (d < d1) {
                d2 = d1; i2 = i1;
                if (d < d0) { d1 = d0; i1 = i0; d0 = d; i0 = j; }
                else        { d1 = d;  i1 = j; }
            } else { d2 = d; i2 = j; }
        }
    }

    float w0 = 1.0f / fmaxf(d0, 1e-16f);
    float w1 = 1.0f / fmaxf(d1, 1e-16f);
    float w2 = 1.0f / fmaxf(d2, 1e-16f);
    float inv = 1.0f / (w0 + w1 + w2);

    gidx[f * 3 + 0] = b * N_COARSE + i0;
    gidx[f * 3 + 1] = b * N_COARSE + i1;
    gidx[f * 3 + 2] = b * N_COARSE + i2;
    gw[f * 3 + 0] = w0 * inv;
    gw[f * 3 + 1] = w1 * inv;
    gw[f * 3 + 2] = w2 * inv;
}

// ---------------------------------------------------------------------------
// Tiled fp32 GEMM: C[M,N] = op(A[M,K] @ B[K,N] [+ bias] [+ gathered interp])
// BM=128, BN=128, BK=8, TM=TN=8, 256 threads
// GATHER epilogue adds sum_k w_k * Y[idx_k][col] (Y stride hardcoded C_HID)
// ---------------------------------------------------------------------------
#define BM 128
#define BN 128
#define BKK 8
#define TM 8
#define TN 8

template <bool BIAS, bool RELU, bool GATHER>
__global__ __launch_bounds__(256) void sgemm_kernel(
    const float* __restrict__ A, const float* __restrict__ Bm,
    const float* __restrict__ bias, float* __restrict__ C,
    int M, int N, int K,
    const float* __restrict__ Y,
    const int* __restrict__ gidx, const float* __restrict__ gw)
{
    __shared__ float As[BKK][BM];
    __shared__ float Bs[BKK][BN];

    const int tid  = threadIdx.x;
    const int row0 = blockIdx.y * BM;
    const int col0 = blockIdx.x * BN;

    const int a_row = tid >> 1;           // 0..127
    const int a_col = (tid & 1) * 4;      // 0 or 4
    const int b_row = tid >> 5;           // 0..7
    const int b_col = (tid & 31) * 4;     // 0..124

    const int ty = tid >> 4;              // 0..15
    const int tx = tid & 15;              // 0..15

    float acc[TM][TN] = {};

    for (int k0 = 0; k0 < K; k0 += BKK) {
        float4 av = *reinterpret_cast<const float4*>(
            &A[(size_t)(row0 + a_row) * K + k0 + a_col]);
        As[a_col + 0][a_row] = av.x;
        As[a_col + 1][a_row] = av.y;
        As[a_col + 2][a_row] = av.z;
        As[a_col + 3][a_row] = av.w;
        float4 bv = *reinterpret_cast<const float4*>(
            &Bm[(size_t)(k0 + b_row) * N + col0 + b_col]);
        *reinterpret_cast<float4*>(&Bs[b_row][b_col]) = bv;
        __syncthreads();

        #pragma unroll
        for (int kk = 0; kk < BKK; kk++) {
            float a[TM], b[TN];
            #pragma unroll
            for (int i = 0; i < TM; i++) a[i] = As[kk][ty * TM + i];
            #pragma unroll
            for (int j = 0; j < TN; j++) b[j] = Bs[kk][tx * TN + j];
            #pragma unroll
            for (int i = 0; i < TM; i++)
                #pragma unroll
                for (int j = 0; j < TN; j++)
                    acc[i][j] = fmaf(a[i], b[j], acc[i][j]);
        }
        __syncthreads();
    }

    #pragma unroll
    for (int i = 0; i < TM; i++) {
        const int r = row0 + ty * TM + i;
        int ii0 = 0, ii1 = 0, ii2 = 0;
        float w0 = 0.f, w1 = 0.f, w2 = 0.f;
        if (GATHER) {
            ii0 = gidx[r * 3 + 0]; ii1 = gidx[r * 3 + 1]; ii2 = gidx[r * 3 + 2];
            w0 = gw[r * 3 + 0]; w1 = gw[r * 3 + 1]; w2 = gw[r * 3 + 2];
        }
        #pragma unroll
        for (int j = 0; j < TN; j += 4) {
            const int c = col0 + tx * TN + j;
            float4 v;
            v.x = acc[i][j + 0]; v.y = acc[i][j + 1];
            v.z = acc[i][j + 2]; v.w = acc[i][j + 3];
            if (BIAS) {
                float4 bb = *reinterpret_cast<const float4*>(&bias[c]);
                v.x += bb.x; v.y += bb.y; v.z += bb.z; v.w += bb.w;
            }
            if (GATHER) {
                float4 y0 = *reinterpret_cast<const float4*>(&Y[(size_t)ii0 * C_HID + c]);
                float4 y1 = *reinterpret_cast<const float4*>(&Y[(size_t)ii1 * C_HID + c]);
                float4 y2 = *reinterpret_cast<const float4*>(&Y[(size_t)ii2 * C_HID + c]);
                v.x += w0 * y0.x + w1 * y1.x + w2 * y2.x;
                v.y += w0 * y0.y + w1 * y1.y + w2 * y2.y;
                v.z += w0 * y0.z + w1 * y1.z + w2 * y2.z;
                v.w += w0 * y0.w + w1 * y1.w + w2 * y2.w;
            }
            if (RELU) {
                v.x = fmaxf(v.x, 0.f); v.y = fmaxf(v.y, 0.f);
                v.z = fmaxf(v.z, 0.f); v.w = fmaxf(v.w, 0.f);
            }
            *reinterpret_cast<float4*>(&C[(size_t)r * N + c]) = v;
        }
    }
}

// batch_skip int32 -> float (for tuple-tail output, if requested)
__global__ void cast_batch_kernel(const int* __restrict__ b, float* __restrict__ out, int n)
{
    int i = blockIdx.x * blockDim.x + threadIdx.x;
    if (i < n) out[i] = (float)b[i];
}

extern "C" void kernel_launch(void* const* d_in, const int* in_sizes, int n_in,
                              void* d_out, int out_size)
{
    (void)in_sizes; (void)n_in;
    const float* x        = (const float*)d_in[0];
    const float* pos      = (const float*)d_in[1];
    const float* x_skip   = (const float*)d_in[2];
    const float* pos_skip = (const float*)d_in[3];
    const float* W1       = (const float*)d_in[4];
    const float* b1       = (const float*)d_in[5];
    const float* W2       = (const float*)d_in[6];
    const float* b2       = (const float*)d_in[7];

    float* y;  float* h1;  int* idx;  float* w;
    cudaGetSymbolAddress((void**)&y,   g_y);
    cudaGetSymbolAddress((void**)&h1,  g_h1);
    cudaGetSymbolAddress((void**)&idx, g_idx);
    cudaGetSymbolAddress((void**)&w,   g_w);

    // 1) kNN + weights
    knn_kernel<<<BATCH * (N_FINE / 128), 128>>>(pos, pos_skip, idx, w);

    // 2) y = x @ W1a  (W1 rows 0..C_IN-1)
    {
        dim3 grid(C_HID / BN, NC_TOT / BM);
        sgemm_kernel<false, false, false><<<grid, 256>>>(
            x, W1, nullptr, y, NC_TOT, C_HID, C_IN, nullptr, nullptr, nullptr);
    }

    // 3) h1 = relu(x_skip @ W1b + interp(y) + b1)   (W1 rows C_IN..C_IN+C_SKIP-1)
    {
        dim3 grid(C_HID / BN, NF_TOT / BM);
        sgemm_kernel<true, true, true><<<grid, 256>>>(
            x_skip, W1 + (size_t)C_IN * C_HID, b1, h1,
            NF_TOT, C_HID, C_SKIP, y, idx, w);
    }

    // 4) out = relu(h1 @ W2 + b2)
    {
        dim3 grid(C_HID / BN, NF_TOT / BM);
        sgemm_kernel<true, true, false><<<grid, 256>>>(
            h1, W2, b2, (float*)d_out,
            NF_TOT, C_HID, C_HID, nullptr, nullptr, nullptr);
    }

    // Tuple tail: (h, pos_skip, batch_skip) — append if the harness expects it
    const long long H_ELEMS   = (long long)NF_TOT * C_HID;     // 16,777,216
    const long long POS_ELEMS = (long long)NF_TOT * 3;         //    196,608
    if ((long long)out_size >= H_ELEMS + POS_ELEMS) {
        cudaMemcpyAsync((float*)d_out + H_ELEMS, pos_skip,
                        POS_ELEMS * sizeof(float), cudaMemcpyDeviceToDevice);
    }
    if ((long long)out_size >= H_ELEMS + POS_ELEMS + NF_TOT) {
        const int* batch_skip = (const int*)d_in[9];
        cast_batch_kernel<<<(NF_TOT + 255) / 256, 256>>>(
            batch_skip, (float*)d_out + H_ELEMS + POS_ELEMS, NF_TOT);
    }
}

// round 3
// speedup vs baseline: 1.3551x; 1.3551x over previous
#include <cuda_runtime.h>
#include <cuda_bf16.h>
#include <cstdint>

#define BATCH    16
#define N_COARSE 1024
#define N_FINE   4096
#define C_IN     256
#define C_SKIP   128
#define C_HID    256
#define NC_TOT   (BATCH * N_COARSE)   // 16384
#define NF_TOT   (BATCH * N_FINE)     // 65536

// ---------------- scratch (static device globals; no runtime alloc) --------
__device__ float          g_y[NC_TOT * C_HID];                 // 16 MB fp32
__device__ int            g_idx[NF_TOT * 3];
__device__ float          g_w[NF_TOT * 3];
__device__ __nv_bfloat16  g_xe[NC_TOT * 3 * C_IN];             // [16384, 768]
__device__ __nv_bfloat16  g_xse[NF_TOT * 3 * C_SKIP];          // [65536, 384]
__device__ __nv_bfloat16  g_h1e[(size_t)NF_TOT * 3 * C_HID];   // [65536, 768]
__device__ __nv_bfloat16  g_w1ae[C_HID * 3 * C_IN];            // [256 n, 768 k]
__device__ __nv_bfloat16  g_w1be[C_HID * 3 * C_SKIP];          // [256 n, 384 k]
__device__ __nv_bfloat16  g_w2e[C_HID * 3 * C_HID];            // [256 n, 768 k]

// ---------------- PTX helpers (all portable, no arch-gated features) --------
__device__ __forceinline__ uint32_t smem_u32(const void* p) {
    return (uint32_t)__cvta_generic_to_shared(p);
}
__device__ __forceinline__ void cp16(uint32_t dst, const void* src) {
    asm volatile("cp.async.cg.shared.global [%0], [%1], 16;" :: "r"(dst), "l"(src));
}
#define CP_COMMIT()  asm volatile("cp.async.commit_group;" ::: "memory")
#define CP_WAIT(n)   asm volatile("cp.async.wait_group %0;" :: "n"(n) : "memory")

__device__ __forceinline__ void mma16816(float* c, const uint32_t* a, const uint32_t* b) {
    asm volatile(
        "mma.sync.aligned.m16n8k16.row.col.f32.bf16.bf16.f32 "
        "{%0,%1,%2,%3}, {%4,%5,%6,%7}, {%8,%9}, {%0,%1,%2,%3};"
        : "+f"(c[0]), "+f"(c[1]), "+f"(c[2]), "+f"(c[3])
        : "r"(a[0]), "r"(a[1]), "r"(a[2]), "r"(a[3]), "r"(b[0]), "r"(b[1]));
}

// ---------------- kNN (k=3) -------------------------------------------------
__global__ __launch_bounds__(128) void knn_kernel(
    const float* __restrict__ pos, const float* __restrict__ pos_skip,
    int* __restrict__ gidx, float* __restrict__ gw)
{
    __shared__ float sx[N_COARSE], sy[N_COARSE], sz[N_COARSE];
    const int chunks = N_FINE / 128;
    const int b = blockIdx.x / chunks;
    const int chunk = blockIdx.x % chunks;
    const int tid = threadIdx.x;

    const float* pc = pos + (size_t)b * N_COARSE * 3;
    for (int i = tid; i < N_COARSE; i += 128) {
        sx[i] = pc[i * 3 + 0]; sy[i] = pc[i * 3 + 1]; sz[i] = pc[i * 3 + 2];
    }
    __syncthreads();

    const int f = b * N_FINE + chunk * 128 + tid;
    const float px = pos_skip[f * 3 + 0];
    const float py = pos_skip[f * 3 + 1];
    const float pz = pos_skip[f * 3 + 2];

    float d0 = 3.4e38f, d1 = 3.4e38f, d2 = 3.4e38f;
    int i0 = 0, i1 = 0, i2 = 0;
    #pragma unroll 4
    for (int j = 0; j < N_COARSE; j++) {
        float dx = px - sx[j], dy = py - sy[j], dz = pz - sz[j];
        float d = dx * dx + dy * dy + dz * dz;
        if (d < d2) {
            if (d < d1) {
                d2 = d1; i2 = i1;
                if (d < d0) { d1 = d0; i1 = i0; d0 = d; i0 = j; }
                else        { d1 = d;  i1 = j; }
            } else { d2 = d; i2 = j; }
        }
    }
    float w0 = 1.0f / fmaxf(d0, 1e-16f);
    float w1 = 1.0f / fmaxf(d1, 1e-16f);
    float w2 = 1.0f / fmaxf(d2, 1e-16f);
    float inv = 1.0f / (w0 + w1 + w2);
    gidx[f * 3 + 0] = b * N_COARSE + i0;
    gidx[f * 3 + 1] = b * N_COARSE + i1;
    gidx[f * 3 + 2] = b * N_COARSE + i2;
    gw[f * 3 + 0] = w0 * inv;
    gw[f * 3 + 1] = w1 * inv;
    gw[f * 3 + 2] = w2 * inv;
}

// ---------------- split-bf16 expansion --------------------------------------
__global__ void expand_act(const float* __restrict__ in, __nv_bfloat16* __restrict__ out,
                           int M, int K)
{
    int i = blockIdx.x * blockDim.x + threadIdx.x;
    if (i >= M * K) return;
    int m = i / K, k = i - m * K;
    float v = in[i];
    __nv_bfloat16 hi = __float2bfloat16(v);
    __nv_bfloat16 lo = __float2bfloat16(v - __bfloat162float(hi));
    __nv_bfloat16* o = out + (size_t)m * 3 * K;
    o[k] = hi; o[K + k] = lo; o[2 * K + k] = hi;
}
__global__ void expand_w(const float* __restrict__ W, __nv_bfloat16* __restrict__ out,
                         int K, int N)
{
    int i = blockIdx.x * blockDim.x + threadIdx.x;
    if (i >= K * N) return;
    int k = i / N, n = i - k * N;
    float v = W[i];
    __nv_bfloat16 hi = __float2bfloat16(v);
    __nv_bfloat16 lo = __float2bfloat16(v - __bfloat162float(hi));
    __nv_bfloat16* o = out + (size_t)n * 3 * K;
    o[k] = hi; o[K + k] = hi; o[2 * K + k] = lo;
}

// ---------------- HMMA GEMM -------------------------------------------------
// C[128,128] per CTA.  A:[M,ld] bf16 row-major, Bw:[N,ld] bf16 (K contiguous).
// 256 threads = 8 warps; warp tile 32x64; BK=32.
// MODE 0: store fp32   MODE 1: bias+gather+relu -> expanded bf16 h1e
// MODE 2: bias+relu -> fp32
#define PITCH 40   // bf16 elements per smem row (80B: 16B-aligned, conflict-free)

template <int MODE>
__global__ __launch_bounds__(256) void mma_gemm(
    const __nv_bfloat16* __restrict__ A, const __nv_bfloat16* __restrict__ Bw,
    const float* __restrict__ bias, float* __restrict__ outf,
    __nv_bfloat16* __restrict__ outh, int ld, int nchunks,
    const float* __restrict__ Y, const int* __restrict__ gidx,
    const float* __restrict__ gw)
{
    __shared__ __align__(16) __nv_bfloat16 sA[2][128 * PITCH];
    __shared__ __align__(16) __nv_bfloat16 sB[2][128 * PITCH];

    const int tid = threadIdx.x;
    const int wid = tid >> 5, lane = tid & 31;
    const int g = lane >> 2, t = lane & 3;
    const int wm = wid & 3, wn = wid >> 2;        // 4 x 2 warp grid
    const int row0 = blockIdx.y * 128, col0 = blockIdx.x * 128;

    // cp.async tile loader: 128 rows x 32 bf16 (64B = 4x16B) per operand
    const int lrow = tid >> 1;                    // 0..127
    const int lq   = (tid & 1) * 2;               // quad pair 0 or 2
    const uint32_t dA0 = smem_u32(&sA[0][lrow * PITCH + lq * 8]);
    const uint32_t dB0 = smem_u32(&sB[0][lrow * PITCH + lq * 8]);
    const __nv_bfloat16* gA = A + (size_t)(row0 + lrow) * ld + lq * 8;
    const __nv_bfloat16* gB = Bw + (size_t)(col0 + lrow) * ld + lq * 8;

    auto load_stage = [&](int st, int k0) {
        uint32_t dA = dA0 + st * (128 * PITCH * 2);
        uint32_t dB = dB0 + st * (128 * PITCH * 2);
        cp16(dA,      gA + k0);
        cp16(dA + 16, gA + k0 + 8);
        cp16(dB,      gB + k0);
        cp16(dB + 16, gB + k0 + 8);
        CP_COMMIT();
    };

    float acc[2][8][4];
    #pragma unroll
    for (int mt = 0; mt < 2; mt++)
        #pragma unroll
        for (int nt = 0; nt < 8; nt++)
            #pragma unroll
            for (int e = 0; e < 4; e++) acc[mt][nt][e] = 0.f;

    load_stage(0, 0);

    for (int c = 0; c < nchunks; c++) {
        if (c + 1 < nchunks) { load_stage((c + 1) & 1, (c + 1) * 32); CP_WAIT(1); }
        else                 { CP_WAIT(0); }
        __syncthreads();

        const __nv_bfloat16* As = sA[c & 1];
        const __nv_bfloat16* Bs = sB[c & 1];
        #pragma unroll
        for (int ks = 0; ks < 2; ks++) {
            const int k0 = ks * 16;
            uint32_t a[2][4], b[8][2];
            #pragma unroll
            for (int mt = 0; mt < 2; mt++) {
                const int r0 = wm * 32 + mt * 16 + g;
                const __nv_bfloat16* p0 = &As[r0 * PITCH + k0 + 2 * t];
                const __nv_bfloat16* p1 = &As[(r0 + 8) * PITCH + k0 + 2 * t];
                a[mt][0] = *(const uint32_t*)p0;
                a[mt][1] = *(const uint32_t*)p1;
                a[mt][2] = *(const uint32_t*)(p0 + 8);
                a[mt][3] = *(const uint32_t*)(p1 + 8);
            }
            #pragma unroll
            for (int nt = 0; nt < 8; nt++) {
                const int n = wn * 64 + nt * 8 + g;
                const __nv_bfloat16* p = &Bs[n * PITCH + k0 + 2 * t];
                b[nt][0] = *(const uint32_t*)p;
                b[nt][1] = *(const uint32_t*)(p + 8);
            }
            #pragma unroll
            for (int mt = 0; mt < 2; mt++)
                #pragma unroll
                for (int nt = 0; nt < 8; nt++)
                    mma16816(acc[mt][nt], a[mt], b[nt]);
        }
        __syncthreads();
    }

    // ---- epilogue: registers -> global ----
    // acc[mt][nt][e]: row = row0 + wm*32 + mt*16 + g + (e>=2 ? 8 : 0)
    //                 col = col0 + wn*64 + nt*8 + 2t + (e&1)
    #pragma unroll
    for (int mt = 0; mt < 2; mt++) {
        #pragma unroll
        for (int half = 0; half < 2; half++) {
            const int r = row0 + wm * 32 + mt * 16 + g + half * 8;
            int i0 = 0, i1 = 0, i2 = 0;
            float w0 = 0.f, w1 = 0.f, w2 = 0.f;
            if (MODE == 1) {
                i0 = gidx[r * 3 + 0]; i1 = gidx[r * 3 + 1]; i2 = gidx[r * 3 + 2];
                w0 = gw[r * 3 + 0]; w1 = gw[r * 3 + 1]; w2 = gw[r * 3 + 2];
            }
            #pragma unroll
            for (int nt = 0; nt < 8; nt++) {
                const int ccol = col0 + wn * 64 + nt * 8 + 2 * t;
                float vx = acc[mt][nt][half * 2 + 0];
                float vy = acc[mt][nt][half * 2 + 1];
                if (MODE == 0) {
                    *(float2*)&outf[(size_t)r * C_HID + ccol] = make_float2(vx, vy);
                } else if (MODE == 2) {
                    float2 bb = *(const float2*)&bias[ccol];
                    vx = fmaxf(vx + bb.x, 0.f);
                    vy = fmaxf(vy + bb.y, 0.f);
                    *(float2*)&outf[(size_t)r * C_HID + ccol] = make_float2(vx, vy);
                } else {
                    float2 bb = *(const float2*)&bias[ccol];
                    float2 y0 = *(const float2*)&Y[(size_t)i0 * C_HID + ccol];
                    float2 y1 = *(const float2*)&Y[(size_t)i1 * C_HID + ccol];
                    float2 y2 = *(const float2*)&Y[(size_t)i2 * C_HID + ccol];
                    vx = fmaxf(vx + bb.x + w0 * y0.x + w1 * y1.x + w2 * y2.x, 0.f);
                    vy = fmaxf(vy + bb.y + w0 * y0.y + w1 * y1.y + w2 * y2.y, 0.f);
                    __nv_bfloat16 hx = __float2bfloat16(vx);
                    __nv_bfloat16 hy = __float2bfloat16(vy);
                    __nv_bfloat162 hi2 = __halves2bfloat162(hx, hy);
                    __nv_bfloat162 lo2 = __halves2bfloat162(
                        __float2bfloat16(vx - __bfloat162float(hx)),
                        __float2bfloat16(vy - __bfloat162float(hy)));
                    const size_t base = (size_t)r * (3 * C_HID) + ccol;
                    *(__nv_bfloat162*)&outh[base]             = hi2;
                    *(__nv_bfloat162*)&outh[base + C_HID]     = lo2;
                    *(__nv_bfloat162*)&outh[base + 2 * C_HID] = hi2;
                }
            }
        }
    }
}

// batch_skip int32 -> float (tuple tail)
__global__ void cast_batch_kernel(const int* __restrict__ b, float* __restrict__ out, int n)
{
    int i = blockIdx.x * blockDim.x + threadIdx.x;
    if (i < n) out[i] = (float)b[i];
}

// ---------------------------------------------------------------------------
extern "C" void kernel_launch(void* const* d_in, const int* in_sizes, int n_in,
                              void* d_out, int out_size)
{
    (void)in_sizes; (void)n_in;
    const float* x        = (const float*)d_in[0];
    const float* pos      = (const float*)d_in[1];
    const float* x_skip   = (const float*)d_in[2];
    const float* pos_skip = (const float*)d_in[3];
    const float* W1       = (const float*)d_in[4];
    const float* b1       = (const float*)d_in[5];
    const float* W2       = (const float*)d_in[6];
    const float* b2       = (const float*)d_in[7];

    float *y, *w; int* idx;
    __nv_bfloat16 *xe, *xse, *h1e, *w1ae, *w1be, *w2e;
    cudaGetSymbolAddress((void**)&y,    g_y);
    cudaGetSymbolAddress((void**)&idx,  g_idx);
    cudaGetSymbolAddress((void**)&w,    g_w);
    cudaGetSymbolAddress((void**)&xe,   g_xe);
    cudaGetSymbolAddress((void**)&xse,  g_xse);
    cudaGetSymbolAddress((void**)&h1e,  g_h1e);
    cudaGetSymbolAddress((void**)&w1ae, g_w1ae);
    cudaGetSymbolAddress((void**)&w1be, g_w1be);
    cudaGetSymbolAddress((void**)&w2e,  g_w2e);

    // expansions + knn
    expand_act<<<(NC_TOT * C_IN + 255) / 256, 256>>>(x, xe, NC_TOT, C_IN);
    expand_act<<<(NF_TOT * C_SKIP + 255) / 256, 256>>>(x_skip, xse, NF_TOT, C_SKIP);
    expand_w<<<(C_IN * C_HID + 255) / 256, 256>>>(W1, w1ae, C_IN, C_HID);
    expand_w<<<(C_SKIP * C_HID + 255) / 256, 256>>>(W1 + (size_t)C_IN * C_HID, w1be, C_SKIP, C_HID);
    expand_w<<<(C_HID * C_HID + 255) / 256, 256>>>(W2, w2e, C_HID, C_HID);
    knn_kernel<<<BATCH * (N_FINE / 128), 128>>>(pos, pos_skip, idx, w);

    // GEMM1: y = x @ W1a     [16384 x 768] * [256 x 768]^T -> fp32 y
    mma_gemm<0><<<dim3(2, NC_TOT / 128), 256>>>(
        xe, w1ae, nullptr, y, nullptr, 3 * C_IN, (3 * C_IN) / 32, nullptr, nullptr, nullptr);

    // GEMM2: h1 = relu(x_skip @ W1b + interp(y) + b1) -> expanded bf16 h1e
    mma_gemm<1><<<dim3(2, NF_TOT / 128), 256>>>(
        xse, w1be, b1, nullptr, h1e, 3 * C_SKIP, (3 * C_SKIP) / 32, y, idx, w);

    // GEMM3: out = relu(h1 @ W2 + b2) -> fp32 d_out
    mma_gemm<2><<<dim3(2, NF_TOT / 128), 256>>>(
        h1e, w2e, b2, (float*)d_out, nullptr, 3 * C_HID, (3 * C_HID) / 32,
        nullptr, nullptr, nullptr);

    // Tuple tail: (h, pos_skip, batch_skip) — append if the harness expects it
    const long long H_ELEMS   = (long long)NF_TOT * C_HID;
    const long long POS_ELEMS = (long long)NF_TOT * 3;
    if ((long long)out_size >= H_ELEMS + POS_ELEMS) {
        cudaMemcpyAsync((float*)d_out + H_ELEMS, pos_skip,
                        POS_ELEMS * sizeof(float), cudaMemcpyDeviceToDevice);
    }
    if ((long long)out_size >= H_ELEMS + POS_ELEMS + NF_TOT) {
        const int* batch_skip = (const int*)d_in[9];
        cast_batch_kernel<<<(NF_TOT + 255) / 256, 256>>>(
            batch_skip, (float*)d_out + H_ELEMS + POS_ELEMS, NF_TOT);
    }
}

// round 4
// speedup vs baseline: 1.5164x; 1.1190x over previous
#include <cuda_runtime.h>
#include <cuda_bf16.h>
#include <cstdint>

#define BATCH    16
#define N_COARSE 1024
#define N_FINE   4096
#define C_IN     256
#define C_SKIP   128
#define C_HID    256
#define NC_TOT   (BATCH * N_COARSE)   // 16384
#define NF_TOT   (BATCH * N_FINE)     // 65536

// ---------------- scratch (static device globals; no runtime alloc) --------
__device__ float          g_y[NC_TOT * C_HID];                 // 16 MB fp32
__device__ int            g_idx[NF_TOT * 3];
__device__ float          g_w[NF_TOT * 3];
__device__ __nv_bfloat16  g_xe[NC_TOT * 3 * C_IN];             // [16384, 768]
__device__ __nv_bfloat16  g_xse[NF_TOT * 3 * C_SKIP];          // [65536, 384]
__device__ __nv_bfloat16  g_h1e[(size_t)NF_TOT * 3 * C_HID];   // [65536, 768]
__device__ __nv_bfloat16  g_w1ae[C_HID * 3 * C_IN];            // [256 n, 768 k]
__device__ __nv_bfloat16  g_w1be[C_HID * 3 * C_SKIP];          // [256 n, 384 k]
__device__ __nv_bfloat16  g_w2e[C_HID * 3 * C_HID];            // [256 n, 768 k]

// ---------------- PTX helpers (portable, no arch-gated features) -----------
__device__ __forceinline__ uint32_t smem_u32(const void* p) {
    return (uint32_t)__cvta_generic_to_shared(p);
}
__device__ __forceinline__ void cp16(uint32_t dst, const void* src) {
    asm volatile("cp.async.cg.shared.global [%0], [%1], 16;" :: "r"(dst), "l"(src));
}
#define CP_COMMIT()  asm volatile("cp.async.commit_group;" ::: "memory")
#define CP_WAIT(n)   asm volatile("cp.async.wait_group %0;" :: "n"(n) : "memory")
#define LDSM4(r, addr) \
    asm volatile("ldmatrix.sync.aligned.m8n8.x4.shared.b16 {%0,%1,%2,%3}, [%4];" \
        : "=r"((r)[0]), "=r"((r)[1]), "=r"((r)[2]), "=r"((r)[3]) : "r"(addr))

__device__ __forceinline__ void mma16816(float* c, const uint32_t* a, const uint32_t* b) {
    asm volatile(
        "mma.sync.aligned.m16n8k16.row.col.f32.bf16.bf16.f32 "
        "{%0,%1,%2,%3}, {%4,%5,%6,%7}, {%8,%9}, {%0,%1,%2,%3};"
        : "+f"(c[0]), "+f"(c[1]), "+f"(c[2]), "+f"(c[3])
        : "r"(a[0]), "r"(a[1]), "r"(a[2]), "r"(a[3]), "r"(b[0]), "r"(b[1]));
}

// ---------------- kNN (k=3) -------------------------------------------------
__global__ __launch_bounds__(128) void knn_kernel(
    const float* __restrict__ pos, const float* __restrict__ pos_skip,
    int* __restrict__ gidx, float* __restrict__ gw)
{
    __shared__ float sx[N_COARSE], sy[N_COARSE], sz[N_COARSE];
    const int chunks = N_FINE / 128;
    const int b = blockIdx.x / chunks;
    const int chunk = blockIdx.x % chunks;
    const int tid = threadIdx.x;

    const float* pc = pos + (size_t)b * N_COARSE * 3;
    for (int i = tid; i < N_COARSE; i += 128) {
        sx[i] = pc[i * 3 + 0]; sy[i] = pc[i * 3 + 1]; sz[i] = pc[i * 3 + 2];
    }
    __syncthreads();

    const int f = b * N_FINE + chunk * 128 + tid;
    const float px = pos_skip[f * 3 + 0];
    const float py = pos_skip[f * 3 + 1];
    const float pz = pos_skip[f * 3 + 2];

    float d0 = 3.4e38f, d1 = 3.4e38f, d2 = 3.4e38f;
    int i0 = 0, i1 = 0, i2 = 0;
    #pragma unroll 4
    for (int j = 0; j < N_COARSE; j++) {
        float dx = px - sx[j], dy = py - sy[j], dz = pz - sz[j];
        float d = dx * dx + dy * dy + dz * dz;
        if (d < d2) {
            if (d < d1) {
                d2 = d1; i2 = i1;
                if (d < d0) { d1 = d0; i1 = i0; d0 = d; i0 = j; }
                else        { d1 = d;  i1 = j; }
            } else { d2 = d; i2 = j; }
        }
    }
    float w0 = 1.0f / fmaxf(d0, 1e-16f);
    float w1 = 1.0f / fmaxf(d1, 1e-16f);
    float w2 = 1.0f / fmaxf(d2, 1e-16f);
    float inv = 1.0f / (w0 + w1 + w2);
    gidx[f * 3 + 0] = b * N_COARSE + i0;
    gidx[f * 3 + 1] = b * N_COARSE + i1;
    gidx[f * 3 + 2] = b * N_COARSE + i2;
    gw[f * 3 + 0] = w0 * inv;
    gw[f * 3 + 1] = w1 * inv;
    gw[f * 3 + 2] = w2 * inv;
}

// ---------------- split-bf16 expansion --------------------------------------
// activations: [M,K] fp32 -> [M,3K] bf16 segments [hi | lo | hi] (vectorized x2)
__global__ void expand_act(const float* __restrict__ in, __nv_bfloat16* __restrict__ out,
                           int M, int K)
{
    int i = blockIdx.x * blockDim.x + threadIdx.x;      // pair index
    int tot = M * (K / 2);
    if (i >= tot) return;
    int kh = K / 2;
    int m = i / kh, kp = i - m * kh;
    float2 v = *(const float2*)(in + (size_t)m * K + kp * 2);
    __nv_bfloat16 hx = __float2bfloat16(v.x), hy = __float2bfloat16(v.y);
    __nv_bfloat162 hi2 = __halves2bfloat162(hx, hy);
    __nv_bfloat162 lo2 = __halves2bfloat162(
        __float2bfloat16(v.x - __bfloat162float(hx)),
        __float2bfloat16(v.y - __bfloat162float(hy)));
    __nv_bfloat16* o = out + (size_t)m * 3 * K + kp * 2;
    *(__nv_bfloat162*)(o)         = hi2;
    *(__nv_bfloat162*)(o + K)     = lo2;
    *(__nv_bfloat162*)(o + 2 * K) = hi2;
}
// all weights in one launch: W1 [384,256] -> w1ae/w1be, W2 [256,256] -> w2e
// output transposed [N, 3K] bf16 with segments [hi | hi | lo]
__global__ void expand_w_all(const float* __restrict__ W1, const float* __restrict__ W2,
                             __nv_bfloat16* __restrict__ w1ae,
                             __nv_bfloat16* __restrict__ w1be,
                             __nv_bfloat16* __restrict__ w2e)
{
    int i = blockIdx.x * blockDim.x + threadIdx.x;
    const int TOT1 = (C_IN + C_SKIP) * C_HID;     // 98304
    const int TOT2 = C_HID * C_HID;               // 65536
    if (i >= TOT1 + TOT2) return;
    float v; __nv_bfloat16* o; int K, k, n;
    if (i < TOT1) {
        k = i / C_HID; n = i - k * C_HID;
        v = W1[i];
        if (k < C_IN) { K = C_IN; o = w1ae + (size_t)n * 3 * K; }
        else          { K = C_SKIP; k -= C_IN; o = w1be + (size_t)n * 3 * K; }
    } else {
        int j = i - TOT1;
        k = j / C_HID; n = j - k * C_HID;
        v = W2[j];
        K = C_HID; o = w2e + (size_t)n * 3 * K;
    }
    __nv_bfloat16 hi = __float2bfloat16(v);
    __nv_bfloat16 lo = __float2bfloat16(v - __bfloat162float(hi));
    o[k] = hi; o[K + k] = hi; o[2 * K + k] = lo;
}

// ---------------- HMMA GEMM (3-stage cp.async + ldmatrix) -------------------
// C[128,128] per CTA.  A:[M,ld] bf16 row-major, Bw:[N,ld] bf16 (K contiguous).
// 256 threads = 8 warps (4x2 grid); warp tile 32x64; BK=32; 3 stages.
// MODE 0: store fp32   MODE 1: bias+gather+relu -> expanded bf16 h1e
// MODE 2: bias+relu -> fp32
#define PITCH 40                        // bf16 per smem row (80B)
#define OP_BYTES (128 * PITCH * 2)      // 10240 per operand per stage
#define STAGE_BYTES (2 * OP_BYTES)      // 20480
#define SM_BYTES (3 * STAGE_BYTES)      // 61440

template <int MODE>
__global__ __launch_bounds__(256, 2) void mma_gemm(
    const __nv_bfloat16* __restrict__ A, const __nv_bfloat16* __restrict__ Bw,
    const float* __restrict__ bias, float* __restrict__ outf,
    __nv_bfloat16* __restrict__ outh, int ld, int nchunks,
    const float* __restrict__ Y, const int* __restrict__ gidx,
    const float* __restrict__ gw)
{
    extern __shared__ __align__(16) char smem[];
    const uint32_t sb = smem_u32(smem);

    const int tid = threadIdx.x;
    const int wid = tid >> 5, lane = tid & 31;
    const int g = lane >> 2, t = lane & 3;
    const int wm = wid & 3, wn = wid >> 2;        // 4 x 2 warp grid
    const int row0 = blockIdx.y * 128, col0 = blockIdx.x * 128;

    // cp.async loader: 128 rows x 32 bf16 (64B) per operand per stage
    const int lrow = tid >> 1;                    // 0..127
    const int lch  = (tid & 1) * 2;               // 16B-chunk 0 or 2
    const uint32_t dA0 = sb + (uint32_t)(lrow * 80 + lch * 16);
    const uint32_t dB0 = dA0 + OP_BYTES;
    const __nv_bfloat16* gA = A + (size_t)(row0 + lrow) * ld + lch * 8;
    const __nv_bfloat16* gB = Bw + (size_t)(col0 + lrow) * ld + lch * 8;

    // ldmatrix base addresses (stage 0)
    uint32_t aAddr[2], bAddr[4];
    #pragma unroll
    for (int mt = 0; mt < 2; mt++)
        aAddr[mt] = sb + (uint32_t)(((wm * 32 + mt * 16 + (lane & 15)) * PITCH
                                     + (lane >> 4) * 8) * 2);
    #pragma unroll
    for (int p = 0; p < 4; p++)
        bAddr[p] = sb + OP_BYTES + (uint32_t)(((wn * 64 + p * 16 + (lane & 7)
                                     + ((lane >> 4) & 1) * 8) * PITCH
                                     + ((lane >> 3) & 1) * 8) * 2);

    float acc[2][8][4];
    #pragma unroll
    for (int mt = 0; mt < 2; mt++)
        #pragma unroll
        for (int nt = 0; nt < 8; nt++)
            #pragma unroll
            for (int e = 0; e < 4; e++) acc[mt][nt][e] = 0.f;

    // prologue: stages 0 and 1
    #pragma unroll
    for (int s = 0; s < 2; s++) {
        const int k0 = s * 32;
        const uint32_t dA = dA0 + s * STAGE_BYTES;
        const uint32_t dB = dB0 + s * STAGE_BYTES;
        cp16(dA, gA + k0); cp16(dA + 16, gA + k0 + 8);
        cp16(dB, gB + k0); cp16(dB + 16, gB + k0 + 8);
        CP_COMMIT();
    }

    int stage = 0, pstage = 2;
    for (int c = 0; c < nchunks; c++) {
        if (c + 1 == nchunks) { CP_WAIT(0); } else { CP_WAIT(1); }
        __syncthreads();

        if (c + 2 < nchunks) {
            const int k0 = (c + 2) * 32;
            const uint32_t dA = dA0 + pstage * STAGE_BYTES;
            const uint32_t dB = dB0 + pstage * STAGE_BYTES;
            cp16(dA, gA + k0); cp16(dA + 16, gA + k0 + 8);
            cp16(dB, gB + k0); cp16(dB + 16, gB + k0 + 8);
            CP_COMMIT();
            pstage = (pstage == 2) ? 0 : pstage + 1;
        }

        const uint32_t so = stage * STAGE_BYTES;
        #pragma unroll
        for (int ks = 0; ks < 2; ks++) {
            const uint32_t ko = so + ks * 32;     // 16 bf16 = 32 bytes
            uint32_t a[2][4], bq[4][4];
            LDSM4(a[0], aAddr[0] + ko);
            LDSM4(a[1], aAddr[1] + ko);
            LDSM4(bq[0], bAddr[0] + ko);
            LDSM4(bq[1], bAddr[1] + ko);
            LDSM4(bq[2], bAddr[2] + ko);
            LDSM4(bq[3], bAddr[3] + ko);
            #pragma unroll
            for (int mt = 0; mt < 2; mt++)
                #pragma unroll
                for (int nt = 0; nt < 8; nt++)
                    mma16816(acc[mt][nt], a[mt], &bq[nt >> 1][(nt & 1) * 2]);
        }
        stage = (stage == 2) ? 0 : stage + 1;
    }

    // ---- epilogue: registers -> global ----
    #pragma unroll
    for (int mt = 0; mt < 2; mt++) {
        #pragma unroll
        for (int half = 0; half < 2; half++) {
            const int r = row0 + wm * 32 + mt * 16 + g + half * 8;
            int i0 = 0, i1 = 0, i2 = 0;
            float w0 = 0.f, w1 = 0.f, w2 = 0.f;
            if (MODE == 1) {
                i0 = gidx[r * 3 + 0]; i1 = gidx[r * 3 + 1]; i2 = gidx[r * 3 + 2];
                w0 = gw[r * 3 + 0]; w1 = gw[r * 3 + 1]; w2 = gw[r * 3 + 2];
            }
            #pragma unroll
            for (int nt = 0; nt < 8; nt++) {
                const int ccol = col0 + wn * 64 + nt * 8 + 2 * t;
                float vx = acc[mt][nt][half * 2 + 0];
                float vy = acc[mt][nt][half * 2 + 1];
                if (MODE == 0) {
                    *(float2*)&outf[(size_t)r * C_HID + ccol] = make_float2(vx, vy);
                } else if (MODE == 2) {
                    float2 bb = *(const float2*)&bias[ccol];
                    vx = fmaxf(vx + bb.x, 0.f);
                    vy = fmaxf(vy + bb.y, 0.f);
                    *(float2*)&outf[(size_t)r * C_HID + ccol] = make_float2(vx, vy);
                } else {
                    float2 bb = *(const float2*)&bias[ccol];
                    float2 y0 = *(const float2*)&Y[(size_t)i0 * C_HID + ccol];
                    float2 y1 = *(const float2*)&Y[(size_t)i1 * C_HID + ccol];
                    float2 y2 = *(const float2*)&Y[(size_t)i2 * C_HID + ccol];
                    vx = fmaxf(vx + bb.x + w0 * y0.x + w1 * y1.x + w2 * y2.x, 0.f);
                    vy = fmaxf(vy + bb.y + w0 * y0.y + w1 * y1.y + w2 * y2.y, 0.f);
                    __nv_bfloat16 hx = __float2bfloat16(vx);
                    __nv_bfloat16 hy = __float2bfloat16(vy);
                    __nv_bfloat162 hi2 = __halves2bfloat162(hx, hy);
                    __nv_bfloat162 lo2 = __halves2bfloat162(
                        __float2bfloat16(vx - __bfloat162float(hx)),
                        __float2bfloat16(vy - __bfloat162float(hy)));
                    const size_t base = (size_t)r * (3 * C_HID) + ccol;
                    *(__nv_bfloat162*)&outh[base]             = hi2;
                    *(__nv_bfloat162*)&outh[base + C_HID]     = lo2;
                    *(__nv_bfloat162*)&outh[base + 2 * C_HID] = hi2;
                }
            }
        }
    }
}

// batch_skip int32 -> float (tuple tail)
__global__ void cast_batch_kernel(const int* __restrict__ b, float* __restrict__ out, int n)
{
    int i = blockIdx.x * blockDim.x + threadIdx.x;
    if (i < n) out[i] = (float)b[i];
}

// ---------------------------------------------------------------------------
extern "C" void kernel_launch(void* const* d_in, const int* in_sizes, int n_in,
                              void* d_out, int out_size)
{
    (void)in_sizes; (void)n_in;
    const float* x        = (const float*)d_in[0];
    const float* pos      = (const float*)d_in[1];
    const float* x_skip   = (const float*)d_in[2];
    const float* pos_skip = (const float*)d_in[3];
    const float* W1       = (const float*)d_in[4];
    const float* b1       = (const float*)d_in[5];
    const float* W2       = (const float*)d_in[6];
    const float* b2       = (const float*)d_in[7];

    float *y, *w; int* idx;
    __nv_bfloat16 *xe, *xse, *h1e, *w1ae, *w1be, *w2e;
    cudaGetSymbolAddress((void**)&y,    g_y);
    cudaGetSymbolAddress((void**)&idx,  g_idx);
    cudaGetSymbolAddress((void**)&w,    g_w);
    cudaGetSymbolAddress((void**)&xe,   g_xe);
    cudaGetSymbolAddress((void**)&xse,  g_xse);
    cudaGetSymbolAddress((void**)&h1e,  g_h1e);
    cudaGetSymbolAddress((void**)&w1ae, g_w1ae);
    cudaGetSymbolAddress((void**)&w1be, g_w1be);
    cudaGetSymbolAddress((void**)&w2e,  g_w2e);

    static bool attr_done = false;
    if (!attr_done) {
        cudaFuncSetAttribute(mma_gemm<0>, cudaFuncAttributeMaxDynamicSharedMemorySize, SM_BYTES);
        cudaFuncSetAttribute(mma_gemm<1>, cudaFuncAttributeMaxDynamicSharedMemorySize, SM_BYTES);
        cudaFuncSetAttribute(mma_gemm<2>, cudaFuncAttributeMaxDynamicSharedMemorySize, SM_BYTES);
        attr_done = true;
    }

    // expansions + knn
    expand_act<<<(NC_TOT * C_IN / 2 + 255) / 256, 256>>>(x, xe, NC_TOT, C_IN);
    expand_act<<<(NF_TOT * C_SKIP / 2 + 255) / 256, 256>>>(x_skip, xse, NF_TOT, C_SKIP);
    expand_w_all<<<((C_IN + C_SKIP + C_HID) * C_HID + 255) / 256, 256>>>(
        W1, W2, w1ae, w1be, w2e);
    knn_kernel<<<BATCH * (N_FINE / 128), 128>>>(pos, pos_skip, idx, w);

    // GEMM1: y = x @ W1a     [16384 x 768] * [256 x 768]^T -> fp32 y
    mma_gemm<0><<<dim3(2, NC_TOT / 128), 256, SM_BYTES>>>(
        xe, w1ae, nullptr, y, nullptr, 3 * C_IN, (3 * C_IN) / 32, nullptr, nullptr, nullptr);

    // GEMM2: h1 = relu(x_skip @ W1b + interp(y) + b1) -> expanded bf16 h1e
    mma_gemm<1><<<dim3(2, NF_TOT / 128), 256, SM_BYTES>>>(
        xse, w1be, b1, nullptr, h1e, 3 * C_SKIP, (3 * C_SKIP) / 32, y, idx, w);

    // GEMM3: out = relu(h1 @ W2 + b2) -> fp32 d_out
    mma_gemm<2><<<dim3(2, NF_TOT / 128), 256, SM_BYTES>>>(
        h1e, w2e, b2, (float*)d_out, nullptr, 3 * C_HID, (3 * C_HID) / 32,
        nullptr, nullptr, nullptr);

    // Tuple tail: (h, pos_skip, batch_skip) — append if the harness expects it
    const long long H_ELEMS   = (long long)NF_TOT * C_HID;
    const long long POS_ELEMS = (long long)NF_TOT * 3;
    if ((long long)out_size >= H_ELEMS + POS_ELEMS) {
        cudaMemcpyAsync((float*)d_out + H_ELEMS, pos_skip,
                        POS_ELEMS * sizeof(float), cudaMemcpyDeviceToDevice);
    }
    if ((long long)out_size >= H_ELEMS + POS_ELEMS + NF_TOT) {
        const int* batch_skip = (const int*)d_in[9];
        cast_batch_kernel<<<(NF_TOT + 255) / 256, 256>>>(
            batch_skip, (float*)d_out + H_ELEMS + POS_ELEMS, NF_TOT);
    }
}